// round 3
// baseline (speedup 1.0000x reference)
#include <cuda_runtime.h>
#include <math.h>

// ---------------- problem constants ----------------
#define D1      512                    // D_IN
#define D2      1024                   // 2*D_IN
#define SEQLEN  4096
#define CHUNK   256
#define NCHUNK  16
#define BATCH   4
#define NROWS   (BATCH*CHUNK)          // 1024 rows per chunk step
#define TOTROWS (BATCH*SEQLEN)         // 16384 rows total
#define LOSS_SCALE (2.0f/((float)NROWS*(float)D1))   // d(mean sq)/dpred factor

// ---------------- device scratch (no allocations allowed) ----------------
__device__ float g_W1 [D1*D2];
__device__ float g_W2 [D2*D1];
__device__ float g_S1 [D1*D2];
__device__ float g_S2 [D2*D1];
__device__ float g_WKV[D1*D2];         // [w_k | w_v] concatenated on columns
__device__ float g_kv [NROWS*D2];      // cols 0..511 = k, 512..1023 = v
__device__ float g_h  [NROWS*D2];      // pre-gelu hidden
__device__ float g_a  [NROWS*D2];      // gelu(h)
__device__ float g_dp [NROWS*D1];      // dLoss/dpred
__device__ float g_dh [NROWS*D2];      // dLoss/dh
__device__ float g_q  [TOTROWS*D1];
__device__ float g_aq [TOTROWS*D2];

// ---------------- math helpers ----------------
__device__ __forceinline__ float gelu_f(float x) {
    return 0.5f * x * (1.0f + erff(x * 0.70710678118654752f));
}
__device__ __forceinline__ float gelu_grad(float x) {
    float cdf = 0.5f * (1.0f + erff(x * 0.70710678118654752f));
    float pdf = 0.3989422804014327f * expf(-0.5f * x * x);
    return cdf + x * pdf;
}
__device__ __forceinline__ float sigmoid_f(float x) { return 1.0f / (1.0f + expf(-x)); }

// ---------------- init: copy weights, zero momentum, build [w_k|w_v] ----------------
__global__ void init_kernel(const float* __restrict__ mw1, const float* __restrict__ mw2,
                            const float* __restrict__ wk,  const float* __restrict__ wv) {
    int i = blockIdx.x * blockDim.x + threadIdx.x;
    if (i < D1 * D2) {
        g_W1[i] = mw1[i];  g_S1[i] = 0.0f;
        g_W2[i] = mw2[i];  g_S2[i] = 0.0f;
        int d = i / D2, j = i % D2;
        g_WKV[i] = (j < D1) ? wk[d * D1 + j] : wv[d * D1 + (j - D1)];
    }
}

// ---------------- generic tiled GEMM with fused epilogues ----------------
// op(A)[M,K] * op(B)[K,N] -> epilogue at [M,N]
//  TA: A stored [K,lda] row-major, op(A)(m,k)=A[k*lda+m]; else A[m*lda+k]
//  TB: B stored [N,ldb] row-major, op(B)(k,n)=B[n*ldb+k]; else B[k*ldb+n]
// EPI: 0 C=acc | 1 C=acc, aux3=gelu(acc) | 2 C=(acc-aux1)*LOSS_SCALE
//      3 C=acc*gelu'(aux1) | 4 S(aux3)=decay*S-lr*acc; W(aux4)=(1-a)W+S | 5 C=gelu(acc)
#define BM 64
#define BN 64
#define BK 16

template<bool TA, bool TB, int EPI>
__global__ __launch_bounds__(256)
void gemm_k(const float* __restrict__ A, const float* __restrict__ B,
            float* __restrict__ C,
            int M, int N, int K, int lda, int ldb, int ldc, int ldaux,
            long long strideA, long long strideC,
            const float* __restrict__ aux1, float* __restrict__ aux3, float* __restrict__ aux4,
            const float* __restrict__ p_alpha, const float* __restrict__ p_lr,
            const float* __restrict__ p_decay) {
    __shared__ float As[BK][BM + 4];
    __shared__ float Bs[BK][BN + 4];

    const float* Ab = A + (size_t)blockIdx.z * strideA;
    float* Cb = C + (size_t)blockIdx.z * strideC;   // only dereferenced when EPI writes C

    const int row0 = blockIdx.y * BM;
    const int col0 = blockIdx.x * BN;
    const int t  = threadIdx.x;
    const int tx = t & 15;         // col group
    const int ty = t >> 4;         // row group

    float acc[4][4] = {};

    for (int k0 = 0; k0 < K; k0 += BK) {
        #pragma unroll
        for (int i = 0; i < 4; i++) {
            int idx = t + i * 256;
            if constexpr (!TA) {
                int m = idx >> 4, kk = idx & 15;
                As[kk][m] = Ab[(size_t)(row0 + m) * lda + (k0 + kk)];
            } else {
                int kk = idx >> 6, m = idx & 63;
                As[kk][m] = Ab[(size_t)(k0 + kk) * lda + (row0 + m)];
            }
        }
        #pragma unroll
        for (int i = 0; i < 4; i++) {
            int idx = t + i * 256;
            if constexpr (!TB) {
                int kk = idx >> 6, n = idx & 63;
                Bs[kk][n] = B[(size_t)(k0 + kk) * ldb + (col0 + n)];
            } else {
                int n = idx >> 4, kk = idx & 15;
                Bs[kk][n] = B[(size_t)(col0 + n) * ldb + (k0 + kk)];
            }
        }
        __syncthreads();
        #pragma unroll
        for (int kk = 0; kk < BK; kk++) {
            float4 av = *reinterpret_cast<const float4*>(&As[kk][ty * 4]);
            float4 bv = *reinterpret_cast<const float4*>(&Bs[kk][tx * 4]);
            float ar[4] = {av.x, av.y, av.z, av.w};
            float br[4] = {bv.x, bv.y, bv.z, bv.w};
            #pragma unroll
            for (int i = 0; i < 4; i++)
                #pragma unroll
                for (int j = 0; j < 4; j++)
                    acc[i][j] = fmaf(ar[i], br[j], acc[i][j]);
        }
        __syncthreads();
    }

    float alpha = 0.f, lr = 0.f, decay = 0.f;
    if constexpr (EPI == 4) {
        alpha = sigmoid_f(*p_alpha);
        lr    = sigmoid_f(*p_lr);
        decay = sigmoid_f(*p_decay);
    }

    #pragma unroll
    for (int i = 0; i < 4; i++) {
        int m = row0 + ty * 4 + i;
        #pragma unroll
        for (int j = 0; j < 4; j++) {
            int n = col0 + tx * 4 + j;
            size_t ci = (size_t)m * ldc + n;
            float v = acc[i][j];
            if constexpr (EPI == 0) {
                Cb[ci] = v;
            } else if constexpr (EPI == 1) {
                Cb[ci] = v;
                aux3[ci] = gelu_f(v);
            } else if constexpr (EPI == 2) {
                Cb[ci] = (v - aux1[(size_t)m * ldaux + n]) * LOSS_SCALE;
            } else if constexpr (EPI == 3) {
                Cb[ci] = v * gelu_grad(aux1[(size_t)m * ldaux + n]);
            } else if constexpr (EPI == 4) {
                float s = decay * aux3[ci] - lr * v;
                aux3[ci] = s;
                aux4[ci] = (1.0f - alpha) * aux4[ci] + s;
            } else if constexpr (EPI == 5) {
                Cb[ci] = gelu_f(v);
            }
        }
    }
}

// ---------------- host driver ----------------
extern "C" void kernel_launch(void* const* d_in, const int* in_sizes, int n_in,
                              void* d_out, int out_size) {
    const float* x     = (const float*)d_in[0];
    const float* w_q   = (const float*)d_in[1];
    const float* w_k   = (const float*)d_in[2];
    const float* w_v   = (const float*)d_in[3];
    const float* mw1   = (const float*)d_in[4];
    const float* mw2   = (const float*)d_in[5];
    const float* p_al  = (const float*)d_in[6];
    const float* p_lr  = (const float*)d_in[7];
    const float* p_dec = (const float*)d_in[8];
    // d_in[9] = update_mem (always 1 for this problem's setup)
    float* out = (float*)d_out;

    float *W1, *W2, *S1, *S2, *WKV, *KV, *H, *Abuf, *DP, *DH, *Q, *AQ;
    cudaGetSymbolAddress((void**)&W1,   g_W1);
    cudaGetSymbolAddress((void**)&W2,   g_W2);
    cudaGetSymbolAddress((void**)&S1,   g_S1);
    cudaGetSymbolAddress((void**)&S2,   g_S2);
    cudaGetSymbolAddress((void**)&WKV,  g_WKV);
    cudaGetSymbolAddress((void**)&KV,   g_kv);
    cudaGetSymbolAddress((void**)&H,    g_h);
    cudaGetSymbolAddress((void**)&Abuf, g_a);
    cudaGetSymbolAddress((void**)&DP,   g_dp);
    cudaGetSymbolAddress((void**)&DH,   g_dh);
    cudaGetSymbolAddress((void**)&Q,    g_q);
    cudaGetSymbolAddress((void**)&AQ,   g_aq);

    init_kernel<<<(D1 * D2 + 255) / 256, 256>>>(mw1, mw2, w_k, w_v);

    for (int c = 0; c < NCHUNK; c++) {
        const float* chunk = x + (size_t)c * CHUNK * D1;   // batch stride handled via strideA

        // kv = chunk @ [w_k|w_v]    [B x 256 x 512] @ [512 x 1024]
        gemm_k<false, false, 0><<<dim3(D2 / BN, CHUNK / BM, BATCH), 256>>>(
            chunk, WKV, KV, CHUNK, D2, D1, D1, D2, D2, 0,
            (long long)SEQLEN * D1, (long long)CHUNK * D2,
            nullptr, nullptr, nullptr, nullptr, nullptr, nullptr);

        // h = k @ W1 ; a = gelu(h)
        gemm_k<false, false, 1><<<dim3(D2 / BN, NROWS / BM, 1), 256>>>(
            KV, W1, H, NROWS, D2, D1, D2, D2, D2, 0, 0, 0,
            nullptr, Abuf, nullptr, nullptr, nullptr, nullptr);

        // dpred = (a @ W2 - v) * 2/(N*D)
        gemm_k<false, false, 2><<<dim3(D1 / BN, NROWS / BM, 1), 256>>>(
            Abuf, W2, DP, NROWS, D1, D2, D2, D1, D1, D2, 0, 0,
            KV + D1 /*v*/, nullptr, nullptr, nullptr, nullptr, nullptr);

        // dh = (dpred @ W2^T) * gelu'(h)   (uses OLD W2)
        gemm_k<false, true, 3><<<dim3(D2 / BN, NROWS / BM, 1), 256>>>(
            DP, W2, DH, NROWS, D2, D1, D1, D1, D2, D2, 0, 0,
            H, nullptr, nullptr, nullptr, nullptr, nullptr);

        // g1 = k^T @ dh ; fused: S1 = decay*S1 - lr*g1 ; W1 = (1-alpha)*W1 + S1
        gemm_k<true, false, 4><<<dim3(D2 / BN, D1 / BM, 1), 256>>>(
            KV, DH, nullptr, D1, D2, NROWS, D2, D2, D2, 0, 0, 0,
            nullptr, S1, W1, p_al, p_lr, p_dec);

        // g2 = a^T @ dpred ; fused update of S2, W2
        gemm_k<true, false, 4><<<dim3(D1 / BN, D2 / BM, 1), 256>>>(
            Abuf, DP, nullptr, D2, D1, NROWS, D2, D1, D1, 0, 0, 0,
            nullptr, S2, W2, p_al, p_lr, p_dec);
    }

    // q = x @ w_q   [16384 x 512] @ [512 x 512]
    gemm_k<false, false, 0><<<dim3(D1 / BN, TOTROWS / BM, 1), 256>>>(
        x, w_q, Q, TOTROWS, D1, D1, D1, D1, D1, 0, 0, 0,
        nullptr, nullptr, nullptr, nullptr, nullptr, nullptr);

    // aq = gelu(q @ W1)
    gemm_k<false, false, 5><<<dim3(D2 / BN, TOTROWS / BM, 1), 256>>>(
        Q, W1, AQ, TOTROWS, D2, D1, D1, D2, D2, 0, 0, 0,
        nullptr, nullptr, nullptr, nullptr, nullptr, nullptr);

    // out = aq @ W2
    gemm_k<false, false, 0><<<dim3(D1 / BN, TOTROWS / BM, 1), 256>>>(
        AQ, W2, out, TOTROWS, D1, D2, D2, D1, D1, 0, 0, 0,
        nullptr, nullptr, nullptr, nullptr, nullptr, nullptr);
}

// round 4
// speedup vs baseline: 1.2851x; 1.2851x over previous
#include <cuda_runtime.h>
#include <math.h>
#include <stdint.h>

// ---------------- problem constants ----------------
#define D1      512                    // D_IN
#define D2      1024                   // 2*D_IN
#define SEQLEN  4096
#define CHUNK   256
#define NCHUNK  16
#define BATCH   4
#define NROWS   (BATCH*CHUNK)          // 1024 rows per chunk step
#define TOTROWS (BATCH*SEQLEN)         // 16384 rows total
#define LOSS_SCALE (2.0f/((float)NROWS*(float)D1))

// ---------------- device scratch ----------------
__device__ float g_W1 [D1*D2];
__device__ float g_W2 [D2*D1];
__device__ float g_S1 [D1*D2];
__device__ float g_S2 [D2*D1];
__device__ float g_WKV[D1*D2];
__device__ float g_kv [NROWS*D2];
__device__ float g_h  [NROWS*D2];
__device__ float g_a  [NROWS*D2];
__device__ float g_dp [NROWS*D1];
__device__ float g_dh [NROWS*D2];
__device__ float g_q  [TOTROWS*D1];
__device__ float g_aq [TOTROWS*D2];

// ---------------- math helpers ----------------
__device__ __forceinline__ float gelu_f(float x) {
    return 0.5f * x * (1.0f + erff(x * 0.70710678118654752f));
}
__device__ __forceinline__ float gelu_grad(float x) {
    float cdf = 0.5f * (1.0f + erff(x * 0.70710678118654752f));
    float pdf = 0.3989422804014327f * expf(-0.5f * x * x);
    return cdf + x * pdf;
}
__device__ __forceinline__ float sigmoid_f(float x) { return 1.0f / (1.0f + expf(-x)); }

// split fp32 into two tf32 values (hi + lo captures ~22 mantissa bits)
__device__ __forceinline__ void split_tf32(float v, uint32_t& hi, uint32_t& lo) {
    uint32_t h;
    asm("cvt.rna.tf32.f32 %0, %1;" : "=r"(h) : "f"(v));
    float hf = __uint_as_float(h);
    float lf = v - hf;
    asm("cvt.rna.tf32.f32 %0, %1;" : "=r"(lo) : "f"(lf));
    hi = h;
}

__device__ __forceinline__ void mma_tf32(float* c, const uint32_t* a, const uint32_t* b) {
    asm volatile(
        "mma.sync.aligned.m16n8k8.row.col.f32.tf32.tf32.f32 "
        "{%0,%1,%2,%3}, {%4,%5,%6,%7}, {%8,%9}, {%0,%1,%2,%3};"
        : "+f"(c[0]), "+f"(c[1]), "+f"(c[2]), "+f"(c[3])
        : "r"(a[0]), "r"(a[1]), "r"(a[2]), "r"(a[3]),
          "r"(b[0]), "r"(b[1]));
}

// ---------------- init ----------------
__global__ void init_kernel(const float* __restrict__ mw1, const float* __restrict__ mw2,
                            const float* __restrict__ wk,  const float* __restrict__ wv) {
    int i = blockIdx.x * blockDim.x + threadIdx.x;
    if (i < D1 * D2) {
        g_W1[i] = mw1[i];  g_S1[i] = 0.0f;
        g_W2[i] = mw2[i];  g_S2[i] = 0.0f;
        int d = i / D2, j = i % D2;
        g_WKV[i] = (j < D1) ? wk[d * D1 + j] : wv[d * D1 + (j - D1)];
    }
}

// ---------------- tensor-core GEMM (3xTF32), fused epilogues ----------------
// op(A)[M,K] * op(B)[K,N]; TA/TB as before.
// EPI: 0 C=acc | 1 C=acc, aux3=gelu(acc) | 2 C=(acc-aux1)*LOSS_SCALE
//      3 C=acc*gelu'(aux1) | 4 S(aux3)=decay*S-lr*acc; W(aux4)=(1-a)W+S | 5 C=gelu(acc)
#define BM 64
#define BN 64
#define BK 32
#define APAD 4   // A row = BK+APAD = 36 words (144B, 16B aligned)
#define BPAD 8   // B row = BN+BPAD = 72 words (288B, 16B aligned)

template<bool TA, bool TB, int EPI>
__global__ __launch_bounds__(128)
void gemm_k(const float* __restrict__ A, const float* __restrict__ B,
            float* __restrict__ C,
            int M, int N, int K, int lda, int ldb, int ldc, int ldaux,
            long long strideA, long long strideC,
            const float* __restrict__ aux1, float* __restrict__ aux3, float* __restrict__ aux4,
            const float* __restrict__ p_alpha, const float* __restrict__ p_lr,
            const float* __restrict__ p_decay) {
    __shared__ float As[BM][BK + APAD];   // m-major: As[m][k]
    __shared__ float Bs[BK][BN + BPAD];   // k-major: Bs[k][n]

    const float* Ab = A + (size_t)blockIdx.z * strideA;
    float* Cb = C + (size_t)blockIdx.z * strideC;

    const int row0 = blockIdx.y * BM;
    const int col0 = blockIdx.x * BN;
    const int t    = threadIdx.x;
    const int lane = t & 31;
    const int warp = t >> 5;
    const int warpRow = (warp >> 1) * 32;   // 2x2 warp grid, each warp 32x32
    const int warpCol = (warp & 1) * 32;
    const int g  = lane >> 2;   // 0..7
    const int t4 = lane & 3;    // 0..3

    float acc[2][4][4];
    #pragma unroll
    for (int i = 0; i < 2; i++)
        #pragma unroll
        for (int j = 0; j < 4; j++)
            #pragma unroll
            for (int r = 0; r < 4; r++) acc[i][j][r] = 0.0f;

    for (int k0 = 0; k0 < K; k0 += BK) {
        // ---- stage A tile (BM x BK) ----
        #pragma unroll
        for (int it = 0; it < 4; it++) {
            int f = t + it * 128;            // 512 float4 groups
            if constexpr (!TA) {
                int m = f >> 3, kk0 = (f & 7) * 4;
                float4 v = *reinterpret_cast<const float4*>(&Ab[(size_t)(row0 + m) * lda + (k0 + kk0)]);
                *reinterpret_cast<float4*>(&As[m][kk0]) = v;
            } else {
                int m0 = (f & 15) * 4, kk = f >> 4;
                float4 v = *reinterpret_cast<const float4*>(&Ab[(size_t)(k0 + kk) * lda + (row0 + m0)]);
                As[m0 + 0][kk] = v.x; As[m0 + 1][kk] = v.y;
                As[m0 + 2][kk] = v.z; As[m0 + 3][kk] = v.w;
            }
        }
        // ---- stage B tile (BK x BN) ----
        #pragma unroll
        for (int it = 0; it < 4; it++) {
            int f = t + it * 128;
            if constexpr (!TB) {
                int n0 = (f & 15) * 4, kk = f >> 4;
                float4 v = *reinterpret_cast<const float4*>(&B[(size_t)(k0 + kk) * ldb + (col0 + n0)]);
                *reinterpret_cast<float4*>(&Bs[kk][n0]) = v;
            } else {
                int kk0 = (f & 7) * 4, n = f >> 3;
                float4 v = *reinterpret_cast<const float4*>(&B[(size_t)(col0 + n) * ldb + (k0 + kk0)]);
                Bs[kk0 + 0][n] = v.x; Bs[kk0 + 1][n] = v.y;
                Bs[kk0 + 2][n] = v.z; Bs[kk0 + 3][n] = v.w;
            }
        }
        __syncthreads();

        // ---- consume: 4 k-steps of 8 ----
        #pragma unroll
        for (int ks = 0; ks < 4; ks++) {
            const int kc = ks * 8 + t4;
            uint32_t ah[2][4], al[2][4], bh[4][2], bl[4][2];
            #pragma unroll
            for (int i = 0; i < 2; i++) {
                const int mB = warpRow + i * 16;
                split_tf32(As[mB + g    ][kc    ], ah[i][0], al[i][0]);
                split_tf32(As[mB + g + 8][kc    ], ah[i][1], al[i][1]);
                split_tf32(As[mB + g    ][kc + 4], ah[i][2], al[i][2]);
                split_tf32(As[mB + g + 8][kc + 4], ah[i][3], al[i][3]);
            }
            #pragma unroll
            for (int j = 0; j < 4; j++) {
                const int nB = warpCol + j * 8 + g;
                split_tf32(Bs[kc    ][nB], bh[j][0], bl[j][0]);
                split_tf32(Bs[kc + 4][nB], bh[j][1], bl[j][1]);
            }
            // 3xTF32: hi*hi, hi*lo, lo*hi  (independent mmas within each pass -> ILP)
            #pragma unroll
            for (int i = 0; i < 2; i++)
                #pragma unroll
                for (int j = 0; j < 4; j++) mma_tf32(acc[i][j], ah[i], bh[j]);
            #pragma unroll
            for (int i = 0; i < 2; i++)
                #pragma unroll
                for (int j = 0; j < 4; j++) mma_tf32(acc[i][j], ah[i], bl[j]);
            #pragma unroll
            for (int i = 0; i < 2; i++)
                #pragma unroll
                for (int j = 0; j < 4; j++) mma_tf32(acc[i][j], al[i], bh[j]);
        }
        __syncthreads();
    }

    float alpha = 0.f, lr = 0.f, decay = 0.f;
    if constexpr (EPI == 4) {
        alpha = sigmoid_f(*p_alpha);
        lr    = sigmoid_f(*p_lr);
        decay = sigmoid_f(*p_decay);
    }

    // ---- epilogue ----
    #pragma unroll
    for (int i = 0; i < 2; i++) {
        const int rA = row0 + warpRow + i * 16 + g;    // rows rA, rA+8
        #pragma unroll
        for (int j = 0; j < 4; j++) {
            const int cA = col0 + warpCol + j * 8 + 2 * t4;   // cols cA, cA+1
            #pragma unroll
            for (int r = 0; r < 4; r++) {
                const int m = rA + (r >= 2 ? 8 : 0);
                const int n = cA + (r & 1);
                const size_t ci = (size_t)m * ldc + n;
                const float v = acc[i][j][r];
                if constexpr (EPI == 0) {
                    Cb[ci] = v;
                } else if constexpr (EPI == 1) {
                    Cb[ci] = v;
                    aux3[ci] = gelu_f(v);
                } else if constexpr (EPI == 2) {
                    Cb[ci] = (v - aux1[(size_t)m * ldaux + n]) * LOSS_SCALE;
                } else if constexpr (EPI == 3) {
                    Cb[ci] = v * gelu_grad(aux1[(size_t)m * ldaux + n]);
                } else if constexpr (EPI == 4) {
                    float s = decay * aux3[ci] - lr * v;
                    aux3[ci] = s;
                    aux4[ci] = (1.0f - alpha) * aux4[ci] + s;
                } else if constexpr (EPI == 5) {
                    Cb[ci] = gelu_f(v);
                }
            }
        }
    }
}

// ---------------- host driver ----------------
extern "C" void kernel_launch(void* const* d_in, const int* in_sizes, int n_in,
                              void* d_out, int out_size) {
    const float* x     = (const float*)d_in[0];
    const float* w_q   = (const float*)d_in[1];
    const float* w_k   = (const float*)d_in[2];
    const float* w_v   = (const float*)d_in[3];
    const float* mw1   = (const float*)d_in[4];
    const float* mw2   = (const float*)d_in[5];
    const float* p_al  = (const float*)d_in[6];
    const float* p_lr  = (const float*)d_in[7];
    const float* p_dec = (const float*)d_in[8];
    float* out = (float*)d_out;

    float *W1, *W2, *S1, *S2, *WKV, *KV, *H, *Abuf, *DP, *DH, *Q, *AQ;
    cudaGetSymbolAddress((void**)&W1,   g_W1);
    cudaGetSymbolAddress((void**)&W2,   g_W2);
    cudaGetSymbolAddress((void**)&S1,   g_S1);
    cudaGetSymbolAddress((void**)&S2,   g_S2);
    cudaGetSymbolAddress((void**)&WKV,  g_WKV);
    cudaGetSymbolAddress((void**)&KV,   g_kv);
    cudaGetSymbolAddress((void**)&H,    g_h);
    cudaGetSymbolAddress((void**)&Abuf, g_a);
    cudaGetSymbolAddress((void**)&DP,   g_dp);
    cudaGetSymbolAddress((void**)&DH,   g_dh);
    cudaGetSymbolAddress((void**)&Q,    g_q);
    cudaGetSymbolAddress((void**)&AQ,   g_aq);

    init_kernel<<<(D1 * D2 + 255) / 256, 256>>>(mw1, mw2, w_k, w_v);

    for (int c = 0; c < NCHUNK; c++) {
        const float* chunk = x + (size_t)c * CHUNK * D1;

        // kv = chunk @ [w_k|w_v]
        gemm_k<false, false, 0><<<dim3(D2 / BN, CHUNK / BM, BATCH), 128>>>(
            chunk, WKV, KV, CHUNK, D2, D1, D1, D2, D2, 0,
            (long long)SEQLEN * D1, (long long)CHUNK * D2,
            nullptr, nullptr, nullptr, nullptr, nullptr, nullptr);

        // h = k @ W1 ; a = gelu(h)
        gemm_k<false, false, 1><<<dim3(D2 / BN, NROWS / BM, 1), 128>>>(
            KV, W1, H, NROWS, D2, D1, D2, D2, D2, 0, 0, 0,
            nullptr, Abuf, nullptr, nullptr, nullptr, nullptr);

        // dpred = (a @ W2 - v) * 2/(N*D)
        gemm_k<false, false, 2><<<dim3(D1 / BN, NROWS / BM, 1), 128>>>(
            Abuf, W2, DP, NROWS, D1, D2, D2, D1, D1, D2, 0, 0,
            KV + D1, nullptr, nullptr, nullptr, nullptr, nullptr);

        // dh = (dpred @ W2^T) * gelu'(h)
        gemm_k<false, true, 3><<<dim3(D2 / BN, NROWS / BM, 1), 128>>>(
            DP, W2, DH, NROWS, D2, D1, D1, D1, D2, D2, 0, 0,
            H, nullptr, nullptr, nullptr, nullptr, nullptr);

        // g1 = k^T @ dh ; fused S1/W1 update
        gemm_k<true, false, 4><<<dim3(D2 / BN, D1 / BM, 1), 128>>>(
            KV, DH, nullptr, D1, D2, NROWS, D2, D2, D2, 0, 0, 0,
            nullptr, S1, W1, p_al, p_lr, p_dec);

        // g2 = a^T @ dpred ; fused S2/W2 update
        gemm_k<true, false, 4><<<dim3(D1 / BN, D2 / BM, 1), 128>>>(
            Abuf, DP, nullptr, D2, D1, NROWS, D2, D1, D1, 0, 0, 0,
            nullptr, S2, W2, p_al, p_lr, p_dec);
    }

    // q = x @ w_q
    gemm_k<false, false, 0><<<dim3(D1 / BN, TOTROWS / BM, 1), 128>>>(
        x, w_q, Q, TOTROWS, D1, D1, D1, D1, D1, 0, 0, 0,
        nullptr, nullptr, nullptr, nullptr, nullptr, nullptr);

    // aq = gelu(q @ W1)
    gemm_k<false, false, 5><<<dim3(D2 / BN, TOTROWS / BM, 1), 128>>>(
        Q, W1, AQ, TOTROWS, D2, D1, D1, D2, D2, 0, 0, 0,
        nullptr, nullptr, nullptr, nullptr, nullptr, nullptr);

    // out = aq @ W2
    gemm_k<false, false, 0><<<dim3(D1 / BN, TOTROWS / BM, 1), 128>>>(
        AQ, W2, out, TOTROWS, D1, D2, D2, D1, D1, 0, 0, 0,
        nullptr, nullptr, nullptr, nullptr, nullptr, nullptr);
}